// round 3
// baseline (speedup 1.0000x reference)
#include <cuda_runtime.h>
#include <math.h>

#define BB    2
#define TT    5
#define CC    64
#define HH    128
#define WW    128
#define H2    64
#define W2    64
#define GG    8
#define KK9   9
#define OFFC  144      // G*2*KK = 8*2*9
#define TCEN  2        // center frame T//2
#define NJ    8        // B*(T-1) jobs
#define HW    (HH*WW)  // 16384
#define HW2   (H2*W2)  // 4096

// ---- scratch (device globals; no allocations allowed) ----
__device__ float g_x2[BB*TT*CC*HW2];          //  2.62M  downsampled frames
__device__ float g_off2[NJ*OFFC*HW2];         //  4.72M  coarse offsets
__device__ float g_off2us[NJ*OFFC*HW];        // 18.87M  upsampled offsets *2
__device__ float g_z1[NJ*CC*HW];              //  8.39M  first deform output
__device__ float g_off1[NJ*OFFC*HW];          // 18.87M  fine offsets
__device__ float g_wa1t[CC*CC*KK9];           // transposed align weights [k][g][o][c]
__device__ float g_waft[CC*CC*KK9];

__device__ __forceinline__ int job_frame(int fi) { return fi + (fi >= TCEN ? 1 : 0); }

// ---------------------------------------------------------------------------
// 1) 2x2 average pool: x -> g_x2
// ---------------------------------------------------------------------------
__global__ void k_downsample(const float* __restrict__ x) {
    int idx = blockIdx.x * blockDim.x + threadIdx.x;
    if (idx >= BB*TT*CC*HW2) return;
    int xx = idx & 63;
    int yy = (idx >> 6) & 63;
    int c  = (idx >> 12) & 63;
    int bt = idx >> 18;                 // b*T + t
    const float* s = x + ((size_t)bt*CC + c)*HW + (yy*2)*WW + xx*2;
    g_x2[idx] = 0.25f * (s[0] + s[1] + s[WW] + s[WW+1]);
}

// ---------------------------------------------------------------------------
// 2) center frame passthrough: out[:,tc] = x[:,tc]
// ---------------------------------------------------------------------------
__global__ void k_center(const float* __restrict__ x, float* __restrict__ out) {
    int idx = blockIdx.x * blockDim.x + threadIdx.x;
    if (idx >= BB*CC*HW) return;                 // C*H*W = 2^20
    int b    = idx >> 20;
    int rest = idx & ((1 << 20) - 1);
    size_t off = ((size_t)(b*TT + TCEN) << 20) + rest;
    out[off] = x[off];
}

// ---------------------------------------------------------------------------
// 3) transpose deform weights (O, G*Cg, 3,3) -> [k][g][o][c] for coalesced
//    per-(g,k) smem slices of 512 floats
// ---------------------------------------------------------------------------
__global__ void k_wtrans(const float* __restrict__ w1, const float* __restrict__ wf) {
    int idx = blockIdx.x * blockDim.x + threadIdx.x;
    if (idx >= CC*CC*KK9) return;
    int c = idx & 7;
    int o = (idx >> 3) & 63;
    int g = (idx >> 9) & 7;
    int k = idx >> 12;                  // 0..8
    int src = (o*CC + g*8 + c)*KK9 + k;
    g_wa1t[idx] = w1[src];
    g_waft[idx] = wf[src];
}

// ---------------------------------------------------------------------------
// 4) conv3x3 pad1 @64x64, Cin=128 (concat fn2|fc2 from g_x2), Cout=144, +bias
//    block: 16x16 thr, 32x32 px tile (2x2 px/thread), 16 co per block
// ---------------------------------------------------------------------------
__global__ void k_conv3(const float* __restrict__ wg, const float* __restrict__ bias) {
    int zc  = blockIdx.z;
    int job = zc / 9, cot = zc % 9;
    int b = job >> 2, fi = job & 3;
    int frame = job_frame(fi);
    int x0 = blockIdx.x * 32, y0 = blockIdx.y * 32;
    int tx = threadIdx.x, ty = threadIdx.y;
    int tid = ty * 16 + tx;

    __shared__ float sIn[34*34];
    __shared__ float sW[16*9];

    float acc[16][4];
    #pragma unroll
    for (int i = 0; i < 16; i++) { acc[i][0]=acc[i][1]=acc[i][2]=acc[i][3]=0.f; }

    const float* srcN = g_x2 + ((b*TT + frame)*CC)*HW2;
    const float* srcC = g_x2 + ((b*TT + TCEN )*CC)*HW2;

    for (int ci = 0; ci < 2*CC; ci++) {
        const float* src = (ci < CC) ? (srcN + ci*HW2) : (srcC + (ci-CC)*HW2);
        for (int l = tid; l < 34*34; l += 256) {
            int ly = l / 34, lx = l % 34;
            int gy = y0 + ly - 1, gx = x0 + lx - 1;
            sIn[l] = (gy >= 0 && gy < H2 && gx >= 0 && gx < W2) ? src[gy*W2 + gx] : 0.f;
        }
        if (tid < 144) {
            int co = tid / 9, k = tid % 9;
            sW[tid] = wg[((cot*16 + co)*(2*CC) + ci)*9 + k];
        }
        __syncthreads();

        int py = ty*2, px = tx*2;
        float r[4][4];
        #pragma unroll
        for (int yy = 0; yy < 4; yy++)
            #pragma unroll
            for (int xx = 0; xx < 4; xx++)
                r[yy][xx] = sIn[(py+yy)*34 + px + xx];

        #pragma unroll
        for (int co = 0; co < 16; co++) {
            #pragma unroll
            for (int k = 0; k < 9; k++) {
                float wv = sW[co*9 + k];
                int ky = k / 3, kx = k % 3;
                acc[co][0] += wv * r[ky  ][kx  ];
                acc[co][1] += wv * r[ky  ][kx+1];
                acc[co][2] += wv * r[ky+1][kx  ];
                acc[co][3] += wv * r[ky+1][kx+1];
            }
        }
        __syncthreads();
    }

    int py = y0 + ty*2, px = x0 + tx*2;
    #pragma unroll
    for (int co = 0; co < 16; co++) {
        int oc = cot*16 + co;
        float bv = bias[oc];
        float* ob = g_off2 + (job*OFFC + oc)*HW2;
        ob[py*W2 + px      ] = acc[co][0] + bv;
        ob[py*W2 + px + 1  ] = acc[co][1] + bv;
        ob[(py+1)*W2 + px  ] = acc[co][2] + bv;
        ob[(py+1)*W2 + px+1] = acc[co][3] + bv;
    }
}

// ---------------------------------------------------------------------------
// 5) bilinear 2x upsample * 2.0 (JAX half-pixel semantics == clamp-to-edge)
// ---------------------------------------------------------------------------
__global__ void k_upsample() {
    int idx = blockIdx.x * blockDim.x + threadIdx.x;
    if (idx >= NJ*OFFC*HW) return;
    int ox = idx & 127;
    int oy = (idx >> 7) & 127;
    int plane = idx >> 14;              // job*144 + ch
    const float* p = g_off2 + plane*HW2;

    float fy = oy*0.5f - 0.25f;
    float fx = ox*0.5f - 0.25f;
    float fy0 = floorf(fy), fx0 = floorf(fx);
    float wy = fy - fy0, wx = fx - fx0;
    int iy = (int)fy0, ix = (int)fx0;
    int y0 = max(0, min(H2-1, iy)),   y1 = max(0, min(H2-1, iy+1));
    int x0 = max(0, min(W2-1, ix)),   x1 = max(0, min(W2-1, ix+1));
    float v = (1.f-wy)*((1.f-wx)*p[y0*W2+x0] + wx*p[y0*W2+x1])
            +      wy *((1.f-wx)*p[y1*W2+x0] + wx*p[y1*W2+x1]);
    g_off2us[idx] = 2.f * v;
}

// ---------------------------------------------------------------------------
// 6) deformable conv (G=8 groups, Cg=8, 3x3, full 64->64 mixing)
//    block: 256 thr, 16x16 px tile; each thread holds all 64 output accs.
//    final_mode=0: offsets=g_off2us, w=g_wa1t, out=g_z1
//    final_mode=1: offsets=g_off1,   w=g_waft, out=d_out frame slot
// ---------------------------------------------------------------------------
__global__ void k_deform(const float* __restrict__ x, float* __restrict__ out, int final_mode) {
    int job = blockIdx.z;
    int b = job >> 2, fi = job & 3;
    int frame = job_frame(fi);

    const float* xf   = x + ((size_t)(b*TT + frame)*CC)*HW;
    const float* offs = (final_mode ? g_off1 : g_off2us) + (size_t)job*OFFC*HW;
    const float* wt   = final_mode ? g_waft : g_wa1t;
    float* ob = final_mode ? (out + ((size_t)(b*TT + frame)*CC)*HW)
                           : (g_z1 + (size_t)job*CC*HW);

    int tid = threadIdx.x;
    int px = blockIdx.x*16 + (tid & 15);
    int py = blockIdx.y*16 + (tid >> 4);
    int p  = py*WW + px;

    __shared__ float sW[512];           // [o][c] for current (g,k)
    float acc[64];
    #pragma unroll
    for (int o = 0; o < 64; o++) acc[o] = 0.f;

    for (int g = 0; g < GG; g++) {
        for (int k = 0; k < KK9; k++) {
            __syncthreads();
            const float* ws = wt + (k*8 + g)*512;
            sW[tid]       = ws[tid];
            sW[tid + 256] = ws[tid + 256];
            __syncthreads();

            int ch = (g*KK9 + k)*2;
            float dy = offs[ch*HW + p];
            float dx = offs[(ch+1)*HW + p];
            float sy = dy + (float)(py + k/3 - 1);
            float sx = dx + (float)(px + k%3 - 1);
            float fy0 = floorf(sy), fx0 = floorf(sx);
            float wy = sy - fy0, wx = sx - fx0;
            int y0 = (int)fy0, xx0 = (int)fx0;
            int y1 = y0 + 1,   xx1 = xx0 + 1;
            bool vy0 = (unsigned)y0  < HH, vy1 = (unsigned)y1  < HH;
            bool vx0 = (unsigned)xx0 < WW, vx1 = (unsigned)xx1 < WW;
            int y0c = min(max(y0, 0), HH-1), y1c = min(max(y1, 0), HH-1);
            int x0c = min(max(xx0,0), WW-1), x1c = min(max(xx1,0), WW-1);
            float w00 = (vy0 && vx0) ? (1.f-wy)*(1.f-wx) : 0.f;
            float w01 = (vy0 && vx1) ? (1.f-wy)*wx       : 0.f;
            float w10 = (vy1 && vx0) ? wy*(1.f-wx)       : 0.f;
            float w11 = (vy1 && vx1) ? wy*wx             : 0.f;
            int o00 = y0c*WW + x0c, o01 = y0c*WW + x1c;
            int o10 = y1c*WW + x0c, o11 = y1c*WW + x1c;

            float s[8];
            const float* xg = xf + (size_t)g*8*HW;
            #pragma unroll
            for (int c = 0; c < 8; c++) {
                const float* xp = xg + c*HW;
                s[c] = w00*__ldg(xp + o00) + w01*__ldg(xp + o01)
                     + w10*__ldg(xp + o10) + w11*__ldg(xp + o11);
            }
            #pragma unroll
            for (int o = 0; o < 64; o++) {
                const float* wr = sW + o*8;
                acc[o] += wr[0]*s[0] + wr[1]*s[1] + wr[2]*s[2] + wr[3]*s[3]
                        + wr[4]*s[4] + wr[5]*s[5] + wr[6]*s[6] + wr[7]*s[7];
            }
        }
    }
    #pragma unroll
    for (int o = 0; o < 64; o++) ob[o*HW + p] = acc[o];
}

// ---------------------------------------------------------------------------
// 7) conv5x5 pad2 @128x128, Cin=128 (concat z1|fc1), Cout=144,
//    + bias + off2_us  -> g_off1
// ---------------------------------------------------------------------------
__global__ void k_conv5(const float* __restrict__ x, const float* __restrict__ wg,
                        const float* __restrict__ bias) {
    int zc  = blockIdx.z;
    int job = zc / 9, cot = zc % 9;
    int b = job >> 2;
    int x0 = blockIdx.x * 32, y0 = blockIdx.y * 32;
    int tx = threadIdx.x, ty = threadIdx.y;
    int tid = ty * 16 + tx;

    __shared__ float sIn[36*36];
    __shared__ float sW[16*25];

    float acc[16][4];
    #pragma unroll
    for (int i = 0; i < 16; i++) { acc[i][0]=acc[i][1]=acc[i][2]=acc[i][3]=0.f; }

    const float* srcZ = g_z1 + (size_t)job*CC*HW;
    const float* srcC = x + ((size_t)(b*TT + TCEN)*CC)*HW;

    for (int ci = 0; ci < 2*CC; ci++) {
        const float* src = (ci < CC) ? (srcZ + ci*HW) : (srcC + (ci-CC)*HW);
        for (int l = tid; l < 36*36; l += 256) {
            int ly = l / 36, lx = l % 36;
            int gy = y0 + ly - 2, gx = x0 + lx - 2;
            sIn[l] = (gy >= 0 && gy < HH && gx >= 0 && gx < WW) ? src[gy*WW + gx] : 0.f;
        }
        for (int l = tid; l < 400; l += 256) {
            int co = l / 25, k = l % 25;
            sW[l] = wg[((cot*16 + co)*(2*CC) + ci)*25 + k];
        }
        __syncthreads();

        int py = ty*2, px = tx*2;
        #pragma unroll
        for (int k = 0; k < 25; k++) {
            int ky = k / 5, kx = k % 5;
            float v00 = sIn[(py+ky  )*36 + px + kx    ];
            float v01 = sIn[(py+ky  )*36 + px + kx + 1];
            float v10 = sIn[(py+ky+1)*36 + px + kx    ];
            float v11 = sIn[(py+ky+1)*36 + px + kx + 1];
            #pragma unroll
            for (int co = 0; co < 16; co++) {
                float wv = sW[co*25 + k];
                acc[co][0] += wv*v00; acc[co][1] += wv*v01;
                acc[co][2] += wv*v10; acc[co][3] += wv*v11;
            }
        }
        __syncthreads();
    }

    int py = y0 + ty*2, px = x0 + tx*2;
    #pragma unroll
    for (int co = 0; co < 16; co++) {
        int oc = cot*16 + co;
        float bv = bias[oc];
        const float* ub = g_off2us + ((size_t)job*OFFC + oc)*HW;
        float*       ob = g_off1   + ((size_t)job*OFFC + oc)*HW;
        int p00 = py*WW + px;
        ob[p00       ] = acc[co][0] + bv + ub[p00       ];
        ob[p00 + 1   ] = acc[co][1] + bv + ub[p00 + 1   ];
        ob[p00 + WW  ] = acc[co][2] + bv + ub[p00 + WW  ];
        ob[p00 + WW+1] = acc[co][3] + bv + ub[p00 + WW+1];
    }
}

// ---------------------------------------------------------------------------
extern "C" void kernel_launch(void* const* d_in, const int* in_sizes, int n_in,
                              void* d_out, int out_size) {
    const float* x        = (const float*)d_in[0];
    const float* w_off1   = (const float*)d_in[1];
    const float* b_off1   = (const float*)d_in[2];
    const float* w_off2   = (const float*)d_in[3];
    const float* b_off2   = (const float*)d_in[4];
    const float* w_align1 = (const float*)d_in[5];
    const float* w_alignf = (const float*)d_in[6];
    float* out = (float*)d_out;

    k_downsample<<<(BB*TT*CC*HW2 + 255)/256, 256>>>(x);
    k_center<<<(BB*CC*HW + 255)/256, 256>>>(x, out);
    k_wtrans<<<(CC*CC*KK9 + 255)/256, 256>>>(w_align1, w_alignf);

    dim3 tb(16, 16);
    k_conv3<<<dim3(2, 2, NJ*9), tb>>>(w_off2, b_off2);
    k_upsample<<<(NJ*OFFC*HW + 255)/256, 256>>>();
    k_deform<<<dim3(8, 8, NJ), 256>>>(x, out, 0);
    k_conv5<<<dim3(4, 4, NJ*9), tb>>>(x, w_off1, b_off1);
    k_deform<<<dim3(8, 8, NJ), 256>>>(x, out, 1);
}